// round 2
// baseline (speedup 1.0000x reference)
#include <cuda_runtime.h>

#define BATCH 2
#define SLEN  8192
#define HID   1024
#define NSEG  4
#define NPTS  512
#define NHEAD 16
#define DHEAD 64
#define WSEG  2048

// Gathered projections, layout [b][seg][h][p][d]
#define GSIZE (BATCH*NSEG*NHEAD*NPTS*DHEAD)   // 4,194,304 floats = 16 MB each
__device__ float g_Qg[GSIZE];
__device__ float g_Kg[GSIZE];
__device__ float g_Vg[GSIZE];

// ---------------------------------------------------------------------------
// Stage 1: sparse projection + gather.
// For residue r, rows j in [0,2048) map to sequence position s = 4j + r.
// Virtual N=768 columns: [0,256)=Q, [256,512)=K, [512,768)=V; within a group,
// m4 = cc/64 selects head h = r + 4*m4, d = cc%64.
// GEMM per (b,r): M=2048, N=768, K=1024.  Tile 128x128, ktile 8, 256 thr, 8x8.
// ---------------------------------------------------------------------------
__global__ __launch_bounds__(256) void proj_kernel(
    const float* __restrict__ X,  const float* __restrict__ Wq,
    const float* __restrict__ bq, const float* __restrict__ Wkv,
    const float* __restrict__ bkv)
{
    __shared__ float Xs[8][128];   // [k][m]
    __shared__ float Ws[8][128];   // [k][n]

    const int tid = threadIdx.x;
    const int b  = blockIdx.z >> 2;
    const int r  = blockIdx.z & 3;
    const int m0 = blockIdx.y * 128;
    const int n0 = blockIdx.x * 128;

    // --- W load mapping (thread loads 4 cols of one k-row per ktile) ---
    const int nn  = (tid & 31) * 4;   // col within tile, multiple of 4 (stays in 64-group)
    const int kkw = tid >> 5;         // 0..7
    const float* wsrc; int wstride;
    {
        int c  = n0 + nn;
        int g  = c >> 8;
        int cc = c & 255;
        int h  = r + 4 * (cc >> 6);
        int d0 = cc & 63;
        if (g == 0)      { wsrc = Wq  + h*64 + d0;        wstride = 1024; }
        else if (g == 1) { wsrc = Wkv + h*64 + d0;        wstride = 2048; }
        else             { wsrc = Wkv + 1024 + h*64 + d0; wstride = 2048; }
    }

    // --- X load mapping (2 threads per row, float4 each) ---
    const int mx = tid >> 1;          // 0..127
    const int kx = (tid & 1) * 4;
    const long xrow = ((long)b * SLEN + (long)(4*(m0 + mx) + r)) * HID;

    float acc[8][8];
    #pragma unroll
    for (int i = 0; i < 8; ++i)
        #pragma unroll
        for (int j = 0; j < 8; ++j) acc[i][j] = 0.f;

    const int tm = (tid >> 4) * 8;
    const int tn = (tid & 15) * 8;

    for (int k0 = 0; k0 < HID; k0 += 8) {
        float4 xv = *(const float4*)(X + xrow + k0 + kx);
        float4 wv = *(const float4*)(wsrc + (long)(k0 + kkw) * wstride);
        __syncthreads();
        Xs[kx+0][mx] = xv.x; Xs[kx+1][mx] = xv.y;
        Xs[kx+2][mx] = xv.z; Xs[kx+3][mx] = xv.w;
        *(float4*)&Ws[kkw][nn] = wv;
        __syncthreads();

        #pragma unroll
        for (int kk = 0; kk < 8; ++kk) {
            float4 a0 = *(const float4*)&Xs[kk][tm];
            float4 a1 = *(const float4*)&Xs[kk][tm+4];
            float4 b0 = *(const float4*)&Ws[kk][tn];
            float4 b1 = *(const float4*)&Ws[kk][tn+4];
            float av[8] = {a0.x,a0.y,a0.z,a0.w,a1.x,a1.y,a1.z,a1.w};
            float bv[8] = {b0.x,b0.y,b0.z,b0.w,b1.x,b1.y,b1.z,b1.w};
            #pragma unroll
            for (int i = 0; i < 8; ++i)
                #pragma unroll
                for (int j = 0; j < 8; ++j)
                    acc[i][j] += av[i] * bv[j];
        }
    }

    // --- epilogue: bias + scatter into gathered layout ---
    #pragma unroll
    for (int i = 0; i < 8; ++i) {
        int jrow = m0 + tm + i;
        int seg  = jrow >> 9;       // j / 512
        int p    = jrow & 511;
        #pragma unroll
        for (int j = 0; j < 8; ++j) {
            int c  = n0 + tn + j;
            int g  = c >> 8;
            int cc = c & 255;
            int h  = r + 4 * (cc >> 6);
            int d  = cc & 63;
            float bias = (g == 0) ? bq[h*64 + d]
                       : (g == 1) ? bkv[h*64 + d]
                                  : bkv[1024 + h*64 + d];
            float v = acc[i][j] + bias;
            float* dst = (g == 0) ? g_Qg : (g == 1) ? g_Kg : g_Vg;
            dst[(((b*NSEG + seg)*NHEAD + h)*NPTS + p)*DHEAD + d] = v;
        }
    }
}

// ---------------------------------------------------------------------------
// Stage 2: attention. One block per (b, seg, h, qtile of 64 rows).
// Full 64x512 score panel in smem (fp32), two-pass softmax, P@V, scattered
// write to d_out at s = seg*2048 + 4*p + (h%4), channel h*64+d.
// Dynamic smem: Qs 64x65 + KVs 64x65 + Sb 64x512 = 164,352 B.
// ---------------------------------------------------------------------------
__device__ __forceinline__ void load_tile65(float* dst, const float* __restrict__ src, int tid)
{
    #pragma unroll
    for (int ps = 0; ps < 4; ++ps) {
        int rr = (tid >> 4) + ps * 16;   // 0..63
        int db = (tid & 15) * 4;         // 0..60
        float4 v = *(const float4*)(src + rr*64 + db);
        dst[rr*65 + db + 0] = v.x;
        dst[rr*65 + db + 1] = v.y;
        dst[rr*65 + db + 2] = v.z;
        dst[rr*65 + db + 3] = v.w;
    }
}

__global__ __launch_bounds__(256) void attn_kernel(float* __restrict__ out)
{
    extern __shared__ float sm[];
    float* Qs  = sm;               // 64*65
    float* KVs = sm + 64*65;       // 64*65
    float* Sb  = sm + 2*64*65;     // 64*512
    __shared__ float rowsum[64];

    const int tid = threadIdx.x;
    const int qt  = blockIdx.x;          // 0..7
    const int h   = blockIdx.y;          // 0..15
    const int bs  = blockIdx.z;          // b*4 + seg
    const int b   = bs >> 2;
    const int seg = bs & 3;
    const long base = (long)(bs*NHEAD + h) * (NPTS * DHEAD);

    // load Q tile (64 rows x 64 d), contiguous in gathered layout
    load_tile65(Qs, g_Qg + base + (long)qt * 64 * 64, tid);

    const int tq = (tid >> 4) * 4;   // 4 q-rows
    const int tk = (tid & 15) * 4;   // 4 k-cols (phase 2) / 4 d-cols (phase 4)
    const float scale = 0.125f;      // 1/sqrt(64)

    // ---- phase 2: S = scale * Q K^T, chunked over k ----
    for (int ck = 0; ck < 8; ++ck) {
        __syncthreads();
        load_tile65(KVs, g_Kg + base + (long)ck * 64 * 64, tid);
        __syncthreads();

        float s4[4][4];
        #pragma unroll
        for (int i = 0; i < 4; ++i)
            #pragma unroll
            for (int j = 0; j < 4; ++j) s4[i][j] = 0.f;

        #pragma unroll 4
        for (int d = 0; d < 64; ++d) {
            float a0 = Qs[(tq+0)*65 + d];
            float a1 = Qs[(tq+1)*65 + d];
            float a2 = Qs[(tq+2)*65 + d];
            float a3 = Qs[(tq+3)*65 + d];
            float c0 = KVs[(tk+0)*65 + d];
            float c1 = KVs[(tk+1)*65 + d];
            float c2 = KVs[(tk+2)*65 + d];
            float c3 = KVs[(tk+3)*65 + d];
            s4[0][0] += a0*c0; s4[0][1] += a0*c1; s4[0][2] += a0*c2; s4[0][3] += a0*c3;
            s4[1][0] += a1*c0; s4[1][1] += a1*c1; s4[1][2] += a1*c2; s4[1][3] += a1*c3;
            s4[2][0] += a2*c0; s4[2][1] += a2*c1; s4[2][2] += a2*c2; s4[2][3] += a2*c3;
            s4[3][0] += a3*c0; s4[3][1] += a3*c1; s4[3][2] += a3*c2; s4[3][3] += a3*c3;
        }
        #pragma unroll
        for (int i = 0; i < 4; ++i)
            #pragma unroll
            for (int j = 0; j < 4; ++j)
                Sb[(tq+i)*512 + ck*64 + tk + j] = s4[i][j] * scale;
    }
    __syncthreads();

    // ---- phase 3: softmax over 512 cols, unnormalized (fold 1/l at end) ----
    {
        int warp = tid >> 5, lane = tid & 31;
        for (int row = warp; row < 64; row += 8) {
            float* srow = Sb + row * 512;
            float mx = -1e30f;
            for (int c = lane; c < 512; c += 32) mx = fmaxf(mx, srow[c]);
            #pragma unroll
            for (int off = 16; off; off >>= 1)
                mx = fmaxf(mx, __shfl_xor_sync(0xffffffffu, mx, off));
            float sum = 0.f;
            for (int c = lane; c < 512; c += 32) {
                float e = __expf(srow[c] - mx);
                srow[c] = e;
                sum += e;
            }
            #pragma unroll
            for (int off = 16; off; off >>= 1)
                sum += __shfl_xor_sync(0xffffffffu, sum, off);
            if (lane == 0) rowsum[row] = sum;
        }
    }

    // ---- phase 4: O = P V, chunked ----
    float o4[4][4];
    #pragma unroll
    for (int i = 0; i < 4; ++i)
        #pragma unroll
        for (int j = 0; j < 4; ++j) o4[i][j] = 0.f;

    for (int ck = 0; ck < 8; ++ck) {
        __syncthreads();
        load_tile65(KVs, g_Vg + base + (long)ck * 64 * 64, tid);
        __syncthreads();

        #pragma unroll 4
        for (int kl = 0; kl < 64; ++kl) {
            int kc = ck*64 + kl;
            float a0 = Sb[(tq+0)*512 + kc];
            float a1 = Sb[(tq+1)*512 + kc];
            float a2 = Sb[(tq+2)*512 + kc];
            float a3 = Sb[(tq+3)*512 + kc];
            float v0 = KVs[kl*65 + tk + 0];
            float v1 = KVs[kl*65 + tk + 1];
            float v2 = KVs[kl*65 + tk + 2];
            float v3 = KVs[kl*65 + tk + 3];
            o4[0][0] += a0*v0; o4[0][1] += a0*v1; o4[0][2] += a0*v2; o4[0][3] += a0*v3;
            o4[1][0] += a1*v0; o4[1][1] += a1*v1; o4[1][2] += a1*v2; o4[1][3] += a1*v3;
            o4[2][0] += a2*v0; o4[2][1] += a2*v1; o4[2][2] += a2*v2; o4[2][3] += a2*v3;
            o4[3][0] += a3*v0; o4[3][1] += a3*v1; o4[3][2] += a3*v2; o4[3][3] += a3*v3;
        }
    }

    // ---- epilogue: normalize + scattered write ----
    #pragma unroll
    for (int i = 0; i < 4; ++i) {
        int p = qt*64 + tq + i;
        int s = seg*WSEG + 4*p + (h & 3);
        float inv = 1.0f / rowsum[tq + i];
        float4 v;
        v.x = o4[i][0] * inv;
        v.y = o4[i][1] * inv;
        v.z = o4[i][2] * inv;
        v.w = o4[i][3] * inv;
        *(float4*)(out + ((long)b * SLEN + s) * HID + h*64 + tk) = v;
    }
}

// ---------------------------------------------------------------------------
extern "C" void kernel_launch(void* const* d_in, const int* in_sizes, int n_in,
                              void* d_out, int out_size)
{
    const float* X   = (const float*)d_in[0];
    const float* Wq  = (const float*)d_in[1];
    const float* bq  = (const float*)d_in[2];
    const float* Wkv = (const float*)d_in[3];
    const float* bkv = (const float*)d_in[4];
    float* out = (float*)d_out;

    // 3/4 of output positions are never written by attention -> zero it all.
    cudaMemsetAsync(out, 0, (size_t)out_size * sizeof(float), 0);

    // Stage 1: sparse projection + gather
    dim3 g1(6, 16, BATCH * 4);     // (N/128, M/128, b*4+r)
    proj_kernel<<<g1, 256>>>(X, Wq, bq, Wkv, bkv);

    // Stage 2: attention
    const int smem = (2*64*65 + 64*512) * (int)sizeof(float);   // 164,352 B
    cudaFuncSetAttribute(attn_kernel, cudaFuncAttributeMaxDynamicSharedMemorySize, smem);
    dim3 g2(8, NHEAD, BATCH * NSEG);   // (qtile, h, b*4+seg)
    attn_kernel<<<g2, 256, smem>>>(out);
}

// round 3
// speedup vs baseline: 1.5428x; 1.5428x over previous
#include <cuda_runtime.h>
#include <cuda_bf16.h>
#include <cstdint>

#define BATCH 2
#define SLEN  8192
#define HID   1024
#define NSEG  4
#define NPTS  512
#define NHEAD 16
#define DHEAD 64
#define WSEG  2048
#define NCOL  768
#define STRB  24   // bf16 elems per smem row (48B: 16B-aligned + conflict-free ldmatrix)

#define GSIZE (BATCH*NSEG*NHEAD*NPTS*DHEAD)
__device__ __align__(16) float g_Qg[GSIZE];
__device__ __align__(16) float g_Kg[GSIZE];
__device__ __align__(16) float g_Vg[GSIZE];
__device__ __align__(16) __nv_bfloat16 g_Xh[BATCH*SLEN*HID];
__device__ __align__(16) __nv_bfloat16 g_Xl[BATCH*SLEN*HID];
__device__ __align__(16) __nv_bfloat16 g_Wp[4*2*NCOL*HID];   // [r][half][n][k]

// ---------------------------------------------------------------------------
__device__ __forceinline__ void ldm_x4(uint32_t* r, uint32_t addr) {
    asm volatile("ldmatrix.sync.aligned.m8n8.x4.shared.b16 {%0,%1,%2,%3}, [%4];\n"
                 : "=r"(r[0]), "=r"(r[1]), "=r"(r[2]), "=r"(r[3]) : "r"(addr));
}
__device__ __forceinline__ void mma16816(float* c, const uint32_t* a,
                                         uint32_t b0, uint32_t b1) {
    asm volatile("mma.sync.aligned.m16n8k16.row.col.f32.bf16.bf16.f32 "
                 "{%0,%1,%2,%3}, {%4,%5,%6,%7}, {%8,%9}, {%0,%1,%2,%3};\n"
                 : "+f"(c[0]), "+f"(c[1]), "+f"(c[2]), "+f"(c[3])
                 : "r"(a[0]), "r"(a[1]), "r"(a[2]), "r"(a[3]), "r"(b0), "r"(b1));
}

// ---------------------------------------------------------------------------
// X -> bf16 hi/lo split
// ---------------------------------------------------------------------------
__global__ __launch_bounds__(256) void splitx(const float4* __restrict__ X4)
{
    long i = (long)blockIdx.x * 256 + threadIdx.x;
    float4 v = X4[i];
    float f[4] = {v.x, v.y, v.z, v.w};
    __nv_bfloat162 h01, h23, l01, l23;
    __nv_bfloat16 h0 = __float2bfloat16_rn(f[0]);
    __nv_bfloat16 h1 = __float2bfloat16_rn(f[1]);
    __nv_bfloat16 h2 = __float2bfloat16_rn(f[2]);
    __nv_bfloat16 h3 = __float2bfloat16_rn(f[3]);
    h01.x = h0; h01.y = h1; h23.x = h2; h23.y = h3;
    l01.x = __float2bfloat16_rn(f[0] - __bfloat162float(h0));
    l01.y = __float2bfloat16_rn(f[1] - __bfloat162float(h1));
    l23.x = __float2bfloat16_rn(f[2] - __bfloat162float(h2));
    l23.y = __float2bfloat16_rn(f[3] - __bfloat162float(h3));
    __nv_bfloat162* H2 = (__nv_bfloat162*)g_Xh;
    __nv_bfloat162* L2 = (__nv_bfloat162*)g_Xl;
    H2[2*i] = h01; H2[2*i+1] = h23;
    L2[2*i] = l01; L2[2*i+1] = l23;
}

// ---------------------------------------------------------------------------
// Pack sparse weight columns into [r][half][n=768][k=1024] bf16 (hi/lo).
// n<256: Q col; [256,512): K; [512,768): V.  h = r + 4*(cc/64), d = cc%64.
// 32x32 smem transpose per block; grid (k/32, n/32, r).
// ---------------------------------------------------------------------------
__global__ __launch_bounds__(256) void wpack(const float* __restrict__ Wq,
                                             const float* __restrict__ Wkv)
{
    __shared__ float s[32][33];
    int tx = threadIdx.x & 31, ty = threadIdx.x >> 5;   // 32 x 8
    int r = blockIdx.z;
    int n = blockIdx.y * 32 + tx;
    int g = n >> 8, cc = n & 255;
    int h = r + 4 * (cc >> 6), d = cc & 63;
    const float* src; long stride;
    if (g == 0)      { src = Wq  + h*64 + d;        stride = 1024; }
    else if (g == 1) { src = Wkv + h*64 + d;        stride = 2048; }
    else             { src = Wkv + 1024 + h*64 + d; stride = 2048; }
    #pragma unroll
    for (int i = 0; i < 4; ++i) {
        int k = blockIdx.x * 32 + ty + i * 8;
        s[ty + i*8][tx] = src[(long)k * stride];
    }
    __syncthreads();
    long rbase = (long)r * 2 * NCOL * HID;
    #pragma unroll
    for (int i = 0; i < 4; ++i) {
        int nl = ty + i * 8;
        float v = s[tx][nl];
        __nv_bfloat16 hi = __float2bfloat16_rn(v);
        __nv_bfloat16 lo = __float2bfloat16_rn(v - __bfloat162float(hi));
        long idx = (long)(blockIdx.y * 32 + nl) * HID + blockIdx.x * 32 + tx;
        g_Wp[rbase + idx] = hi;
        g_Wp[rbase + (long)NCOL * HID + idx] = lo;
    }
}

// ---------------------------------------------------------------------------
// proj via bf16x3 mma: per (b,r) GEMM M=2048 N=768 K=1024, 128x128 block,
// k16 steps double-buffered, 8 warps (2x4), warp tile 64x32.
// Epilogue: +bias, scatter into gathered [b][seg][h][p][d] layout.
// ---------------------------------------------------------------------------
__global__ __launch_bounds__(256) void proj_mma(const float* __restrict__ bq,
                                                const float* __restrict__ bkv)
{
    __shared__ __nv_bfloat16 sA[2][2][128*STRB];   // [buf][half][row*STRB]
    __shared__ __nv_bfloat16 sB[2][2][128*STRB];

    const int tid  = threadIdx.x;
    const int lane = tid & 31, warp = tid >> 5;
    const int wm = warp >> 2, wn = warp & 3;
    const int b  = blockIdx.z >> 2;
    const int r  = blockIdx.z & 3;
    const int m0 = blockIdx.y * 128;
    const int n0 = blockIdx.x * 128;

    // global load mapping: 256 threads -> (128 rows) x (hi/lo), 32B each
    const int lrow = tid & 127, lhalf = tid >> 7;
    const __nv_bfloat16* aSrc =
        (lhalf ? g_Xl : g_Xh) + ((long)b * SLEN + (4*(m0 + lrow) + r)) * HID;
    const __nv_bfloat16* bSrc =
        g_Wp + ((long)(r*2 + lhalf) * NCOL + n0 + lrow) * HID;

    // ldmatrix per-lane byte offsets
    const int lrow16 = (lane & 7) + ((lane >> 3) & 1) * 8;   // 0..15
    const int kbyt   = (lane >> 4) * 16;
    const uint32_t smA = (uint32_t)__cvta_generic_to_shared(&sA[0][0][0]);
    const uint32_t smB = (uint32_t)__cvta_generic_to_shared(&sB[0][0][0]);
    const uint32_t aoff = (uint32_t)((wm*64 + lrow16) * STRB * 2 + kbyt);
    const uint32_t boff = (uint32_t)((wn*32 + lrow16) * STRB * 2 + kbyt);

    float acc[4][4][4];
    #pragma unroll
    for (int i = 0; i < 4; ++i)
        #pragma unroll
        for (int j = 0; j < 4; ++j)
            #pragma unroll
            for (int q = 0; q < 4; ++q) acc[i][j][q] = 0.f;

    // preload k-step 0
    uint4 ra0 = *(const uint4*)(aSrc + 0);
    uint4 ra1 = *(const uint4*)(aSrc + 8);
    uint4 rb0 = *(const uint4*)(bSrc + 0);
    uint4 rb1 = *(const uint4*)(bSrc + 8);
    {
        uint4* dA = (uint4*)&sA[0][lhalf][lrow * STRB];
        dA[0] = ra0; dA[1] = ra1;
        uint4* dB = (uint4*)&sB[0][lhalf][lrow * STRB];
        dB[0] = rb0; dB[1] = rb1;
    }
    __syncthreads();

    for (int kt = 0; kt < 64; ++kt) {
        const int cur = kt & 1;
        if (kt < 63) {
            int k0 = (kt + 1) * 16;
            ra0 = *(const uint4*)(aSrc + k0);
            ra1 = *(const uint4*)(aSrc + k0 + 8);
            rb0 = *(const uint4*)(bSrc + k0);
            rb1 = *(const uint4*)(bSrc + k0 + 8);
        }

        const uint32_t aH = smA + (uint32_t)cur * 12288;
        const uint32_t aL = aH + 6144;
        const uint32_t bH = smB + (uint32_t)cur * 12288;
        const uint32_t bL = bH + 6144;

        uint32_t fbh[2][4], fbl[2][4];
        ldm_x4(fbh[0], bH + boff);
        ldm_x4(fbh[1], bH + boff + 16*STRB*2);
        ldm_x4(fbl[0], bL + boff);
        ldm_x4(fbl[1], bL + boff + 16*STRB*2);

        #pragma unroll
        for (int mi = 0; mi < 4; ++mi) {
            uint32_t fah[4], fal[4];
            ldm_x4(fah, aH + aoff + mi * 16*STRB*2);
            ldm_x4(fal, aL + aoff + mi * 16*STRB*2);
            #pragma unroll
            for (int nj = 0; nj < 4; ++nj) {
                int t = nj >> 1, s = nj & 1;
                float* c = acc[mi][nj];
                mma16816(c, fah, fbh[t][s], fbh[t][s+2]);
                mma16816(c, fah, fbl[t][s], fbl[t][s+2]);
                mma16816(c, fal, fbh[t][s], fbh[t][s+2]);
            }
        }

        if (kt < 63) {
            uint4* dA = (uint4*)&sA[cur ^ 1][lhalf][lrow * STRB];
            dA[0] = ra0; dA[1] = ra1;
            uint4* dB = (uint4*)&sB[cur ^ 1][lhalf][lrow * STRB];
            dB[0] = rb0; dB[1] = rb1;
            __syncthreads();
        }
    }

    // epilogue: bias + scatter (gathered layout)
    const int group = lane >> 2, tig = lane & 3;
    #pragma unroll
    for (int mi = 0; mi < 4; ++mi) {
        #pragma unroll
        for (int nj = 0; nj < 4; ++nj) {
            int nl = wn*32 + nj*8 + tig*2;
            int c  = n0 + nl;
            int g  = c >> 8, cc = c & 255;
            int h  = r + 4 * (cc >> 6), d = cc & 63;
            const float* barr = (g == 0) ? bq : (g == 1) ? bkv : bkv + 1024;
            float b0 = barr[h*64 + d], b1 = barr[h*64 + d + 1];
            float* dst = (g == 0) ? g_Qg : (g == 1) ? g_Kg : g_Vg;
            #pragma unroll
            for (int half = 0; half < 2; ++half) {
                int jrow = m0 + wm*64 + mi*16 + group + half*8;
                int seg = jrow >> 9, p = jrow & 511;
                float2 v;
                v.x = acc[mi][nj][half*2 + 0] + b0;
                v.y = acc[mi][nj][half*2 + 1] + b1;
                *(float2*)&dst[(((b*NSEG + seg)*NHEAD + h)*NPTS + p)*DHEAD + d] = v;
            }
        }
    }
}

// ---------------------------------------------------------------------------
// Stage 2: attention (unchanged from passing R2 kernel).
// ---------------------------------------------------------------------------
__device__ __forceinline__ void load_tile65(float* dst, const float* __restrict__ src, int tid)
{
    #pragma unroll
    for (int ps = 0; ps < 4; ++ps) {
        int rr = (tid >> 4) + ps * 16;
        int db = (tid & 15) * 4;
        float4 v = *(const float4*)(src + rr*64 + db);
        dst[rr*65 + db + 0] = v.x;
        dst[rr*65 + db + 1] = v.y;
        dst[rr*65 + db + 2] = v.z;
        dst[rr*65 + db + 3] = v.w;
    }
}

__global__ __launch_bounds__(256) void attn_kernel(float* __restrict__ out)
{
    extern __shared__ float sm[];
    float* Qs  = sm;
    float* KVs = sm + 64*65;
    float* Sb  = sm + 2*64*65;
    __shared__ float rowsum[64];

    const int tid = threadIdx.x;
    const int qt  = blockIdx.x;
    const int h   = blockIdx.y;
    const int bs  = blockIdx.z;
    const int b   = bs >> 2;
    const int seg = bs & 3;
    const long base = (long)(bs*NHEAD + h) * (NPTS * DHEAD);

    load_tile65(Qs, g_Qg + base + (long)qt * 64 * 64, tid);

    const int tq = (tid >> 4) * 4;
    const int tk = (tid & 15) * 4;
    const float scale = 0.125f;

    for (int ck = 0; ck < 8; ++ck) {
        __syncthreads();
        load_tile65(KVs, g_Kg + base + (long)ck * 64 * 64, tid);
        __syncthreads();

        float s4[4][4];
        #pragma unroll
        for (int i = 0; i < 4; ++i)
            #pragma unroll
            for (int j = 0; j < 4; ++j) s4[i][j] = 0.f;

        #pragma unroll 4
        for (int d = 0; d < 64; ++d) {
            float a0 = Qs[(tq+0)*65 + d];
            float a1 = Qs[(tq+1)*65 + d];
            float a2 = Qs[(tq+2)*65 + d];
            float a3 = Qs[(tq+3)*65 + d];
            float c0 = KVs[(tk+0)*65 + d];
            float c1 = KVs[(tk+1)*65 + d];
            float c2 = KVs[(tk+2)*65 + d];
            float c3 = KVs[(tk+3)*65 + d];
            s4[0][0] += a0*c0; s4[0][1] += a0*c1; s4[0][2] += a0*c2; s4[0][3] += a0*c3;
            s4[1][0] += a1*c0; s4[1][1] += a1*c1; s4[1][2] += a1*c2; s4[1][3] += a1*c3;
            s4[2][0] += a2*c0; s4[2][1] += a2*c1; s4[2][2] += a2*c2; s4[2][3] += a2*c3;
            s4[3][0] += a3*c0; s4[3][1] += a3*c1; s4[3][2] += a3*c2; s4[3][3] += a3*c3;
        }
        #pragma unroll
        for (int i = 0; i < 4; ++i)
            #pragma unroll
            for (int j = 0; j < 4; ++j)
                Sb[(tq+i)*512 + ck*64 + tk + j] = s4[i][j] * scale;
    }
    __syncthreads();

    {
        int warp = tid >> 5, lane = tid & 31;
        for (int row = warp; row < 64; row += 8) {
            float* srow = Sb + row * 512;
            float mx = -1e30f;
            for (int c = lane; c < 512; c += 32) mx = fmaxf(mx, srow[c]);
            #pragma unroll
            for (int off = 16; off; off >>= 1)
                mx = fmaxf(mx, __shfl_xor_sync(0xffffffffu, mx, off));
            float sum = 0.f;
            for (int c = lane; c < 512; c += 32) {
                float e = __expf(srow[c] - mx);
                srow[c] = e;
                sum += e;
            }
            #pragma unroll
            for (int off = 16; off; off >>= 1)
                sum += __shfl_xor_sync(0xffffffffu, sum, off);
            if (lane == 0) rowsum[row] = sum;
        }
    }

    float o4[4][4];
    #pragma unroll
    for (int i = 0; i < 4; ++i)
        #pragma unroll
        for (int j = 0; j < 4; ++j) o4[i][j] = 0.f;

    for (int ck = 0; ck < 8; ++ck) {
        __syncthreads();
        load_tile65(KVs, g_Vg + base + (long)ck * 64 * 64, tid);
        __syncthreads();

        #pragma unroll 4
        for (int kl = 0; kl < 64; ++kl) {
            int kc = ck*64 + kl;
            float a0 = Sb[(tq+0)*512 + kc];
            float a1 = Sb[(tq+1)*512 + kc];
            float a2 = Sb[(tq+2)*512 + kc];
            float a3 = Sb[(tq+3)*512 + kc];
            float v0 = KVs[kl*65 + tk + 0];
            float v1 = KVs[kl*65 + tk + 1];
            float v2 = KVs[kl*65 + tk + 2];
            float v3 = KVs[kl*65 + tk + 3];
            o4[0][0] += a0*v0; o4[0][1] += a0*v1; o4[0][2] += a0*v2; o4[0][3] += a0*v3;
            o4[1][0] += a1*v0; o4[1][1] += a1*v1; o4[1][2] += a1*v2; o4[1][3] += a1*v3;
            o4[2][0] += a2*v0; o4[2][1] += a2*v1; o4[2][2] += a2*v2; o4[2][3] += a2*v3;
            o4[3][0] += a3*v0; o4[3][1] += a3*v1; o4[3][2] += a3*v2; o4[3][3] += a3*v3;
        }
    }

    #pragma unroll
    for (int i = 0; i < 4; ++i) {
        int p = qt*64 + tq + i;
        int s = seg*WSEG + 4*p + (h & 3);
        float inv = 1.0f / rowsum[tq + i];
        float4 v;
        v.x = o4[i][0] * inv;
        v.y = o4[i][1] * inv;
        v.z = o4[i][2] * inv;
        v.w = o4[i][3] * inv;
        *(float4*)(out + ((long)b * SLEN + s) * HID + h*64 + tk) = v;
    }
}

// ---------------------------------------------------------------------------
extern "C" void kernel_launch(void* const* d_in, const int* in_sizes, int n_in,
                              void* d_out, int out_size)
{
    const float* X   = (const float*)d_in[0];
    const float* Wq  = (const float*)d_in[1];
    const float* bq  = (const float*)d_in[2];
    const float* Wkv = (const float*)d_in[3];
    const float* bkv = (const float*)d_in[4];
    float* out = (float*)d_out;

    cudaMemsetAsync(out, 0, (size_t)out_size * sizeof(float), 0);

    // X hi/lo split
    splitx<<<BATCH*SLEN*HID/4/256, 256>>>((const float4*)X);

    // weight pack: (k/32, n/32, r)
    dim3 gw(HID/32, NCOL/32, 4);
    wpack<<<gw, 256>>>(Wq, Wkv);

    // projection (tensor cores)
    dim3 g1(NCOL/128, 16, BATCH * 4);
    proj_mma<<<g1, 256>>>(bq, bkv);

    // attention
    const int smem = (2*64*65 + 64*512) * (int)sizeof(float);
    cudaFuncSetAttribute(attn_kernel, cudaFuncAttributeMaxDynamicSharedMemorySize, smem);
    dim3 g2(8, NHEAD, BATCH * NSEG);
    attn_kernel<<<g2, 256, smem>>>(out);
}

// round 4
// speedup vs baseline: 2.1613x; 1.4009x over previous
#include <cuda_runtime.h>
#include <cuda_bf16.h>
#include <cstdint>

#define BATCH 2
#define SLEN  8192
#define HID   1024
#define NSEG  4
#define NPTS  512
#define NHEAD 16
#define DHEAD 64
#define WSEG  2048
#define NCOL  768
#define STRB  24   // proj smem stride (bf16)
#define STR   72   // attn smem stride (bf16), 144B: conflict-free ldmatrix

#define GSIZE (BATCH*NSEG*NHEAD*NPTS*DHEAD)
__device__ __align__(16) __nv_bfloat16 g_Xh[BATCH*SLEN*HID];
__device__ __align__(16) __nv_bfloat16 g_Xl[BATCH*SLEN*HID];
__device__ __align__(16) __nv_bfloat16 g_Wp[4*2*NCOL*HID];   // [r][half][n][k]
__device__ __align__(16) __nv_bfloat16 g_Qh[GSIZE], g_Ql[GSIZE];   // [b][seg][h][p][d], pre-scaled
__device__ __align__(16) __nv_bfloat16 g_Kh[GSIZE], g_Kl[GSIZE];   // [b][seg][h][p][d]
__device__ __align__(16) __nv_bfloat16 g_Vth[GSIZE], g_Vtl[GSIZE]; // [b][seg][h][d][p]

// ---------------------------------------------------------------------------
__device__ __forceinline__ void ldm_x4(uint32_t* r, uint32_t addr) {
    asm volatile("ldmatrix.sync.aligned.m8n8.x4.shared.b16 {%0,%1,%2,%3}, [%4];\n"
                 : "=r"(r[0]), "=r"(r[1]), "=r"(r[2]), "=r"(r[3]) : "r"(addr));
}
__device__ __forceinline__ void mma16816(float* c, const uint32_t* a,
                                         uint32_t b0, uint32_t b1) {
    asm volatile("mma.sync.aligned.m16n8k16.row.col.f32.bf16.bf16.f32 "
                 "{%0,%1,%2,%3}, {%4,%5,%6,%7}, {%8,%9}, {%0,%1,%2,%3};\n"
                 : "+f"(c[0]), "+f"(c[1]), "+f"(c[2]), "+f"(c[3])
                 : "r"(a[0]), "r"(a[1]), "r"(a[2]), "r"(a[3]), "r"(b0), "r"(b1));
}
__device__ __forceinline__ void cp16(uint32_t dst, const void* src) {
    asm volatile("cp.async.cg.shared.global [%0], [%1], 16;\n" :: "r"(dst), "l"(src));
}
__device__ __forceinline__ void cp_commit() { asm volatile("cp.async.commit_group;\n"); }
__device__ __forceinline__ void cp_waitall() { asm volatile("cp.async.wait_group 0;\n"); }

__device__ __forceinline__ void pack_hl(float x, float y, uint32_t& hi, uint32_t& lo) {
    __nv_bfloat162 h2; h2.x = __float2bfloat16_rn(x); h2.y = __float2bfloat16_rn(y);
    __nv_bfloat162 l2;
    l2.x = __float2bfloat16_rn(x - __bfloat162float(h2.x));
    l2.y = __float2bfloat16_rn(y - __bfloat162float(h2.y));
    hi = *(uint32_t*)&h2; lo = *(uint32_t*)&l2;
}

// ---------------------------------------------------------------------------
__global__ __launch_bounds__(256) void splitx(const float4* __restrict__ X4)
{
    long i = (long)blockIdx.x * 256 + threadIdx.x;
    float4 v = X4[i];
    __nv_bfloat162 h01, h23, l01, l23;
    h01.x = __float2bfloat16_rn(v.x); h01.y = __float2bfloat16_rn(v.y);
    h23.x = __float2bfloat16_rn(v.z); h23.y = __float2bfloat16_rn(v.w);
    l01.x = __float2bfloat16_rn(v.x - __bfloat162float(h01.x));
    l01.y = __float2bfloat16_rn(v.y - __bfloat162float(h01.y));
    l23.x = __float2bfloat16_rn(v.z - __bfloat162float(h23.x));
    l23.y = __float2bfloat16_rn(v.w - __bfloat162float(h23.y));
    __nv_bfloat162* H2 = (__nv_bfloat162*)g_Xh;
    __nv_bfloat162* L2 = (__nv_bfloat162*)g_Xl;
    H2[2*i] = h01; H2[2*i+1] = h23;
    L2[2*i] = l01; L2[2*i+1] = l23;
}

// ---------------------------------------------------------------------------
__global__ __launch_bounds__(256) void wpack(const float* __restrict__ Wq,
                                             const float* __restrict__ Wkv)
{
    __shared__ float s[32][33];
    int tx = threadIdx.x & 31, ty = threadIdx.x >> 5;
    int r = blockIdx.z;
    int n = blockIdx.y * 32 + tx;
    int g = n >> 8, cc = n & 255;
    int h = r + 4 * (cc >> 6), d = cc & 63;
    const float* src; long stride;
    if (g == 0)      { src = Wq  + h*64 + d;        stride = 1024; }
    else if (g == 1) { src = Wkv + h*64 + d;        stride = 2048; }
    else             { src = Wkv + 1024 + h*64 + d; stride = 2048; }
    #pragma unroll
    for (int i = 0; i < 4; ++i) {
        int k = blockIdx.x * 32 + ty + i * 8;
        s[ty + i*8][tx] = src[(long)k * stride];
    }
    __syncthreads();
    long rbase = (long)r * 2 * NCOL * HID;
    #pragma unroll
    for (int i = 0; i < 4; ++i) {
        int nl = ty + i * 8;
        float v = s[tx][nl];
        __nv_bfloat16 hi = __float2bfloat16_rn(v);
        __nv_bfloat16 lo = __float2bfloat16_rn(v - __bfloat162float(hi));
        long idx = (long)(blockIdx.y * 32 + nl) * HID + blockIdx.x * 32 + tx;
        g_Wp[rbase + idx] = hi;
        g_Wp[rbase + (long)NCOL * HID + idx] = lo;
    }
}

// ---------------------------------------------------------------------------
// proj via bf16x3 mma; epilogue writes bf16 hi/lo (Q scaled by 1/8, V transposed)
// ---------------------------------------------------------------------------
__global__ __launch_bounds__(256) void proj_mma(const float* __restrict__ bq,
                                                const float* __restrict__ bkv)
{
    __shared__ __nv_bfloat16 sA[2][2][128*STRB];
    __shared__ __nv_bfloat16 sB[2][2][128*STRB];

    const int tid  = threadIdx.x;
    const int lane = tid & 31, warp = tid >> 5;
    const int wm = warp >> 2, wn = warp & 3;
    const int b  = blockIdx.z >> 2;
    const int r  = blockIdx.z & 3;
    const int m0 = blockIdx.y * 128;
    const int n0 = blockIdx.x * 128;

    const int lrow = tid & 127, lhalf = tid >> 7;
    const __nv_bfloat16* aSrc =
        (lhalf ? g_Xl : g_Xh) + ((long)b * SLEN + (4*(m0 + lrow) + r)) * HID;
    const __nv_bfloat16* bSrc =
        g_Wp + ((long)(r*2 + lhalf) * NCOL + n0 + lrow) * HID;

    const int lrow16 = (lane & 7) + ((lane >> 3) & 1) * 8;
    const int kbyt   = (lane >> 4) * 16;
    const uint32_t smA = (uint32_t)__cvta_generic_to_shared(&sA[0][0][0]);
    const uint32_t smB = (uint32_t)__cvta_generic_to_shared(&sB[0][0][0]);
    const uint32_t aoff = (uint32_t)((wm*64 + lrow16) * STRB * 2 + kbyt);
    const uint32_t boff = (uint32_t)((wn*32 + lrow16) * STRB * 2 + kbyt);

    float acc[4][4][4];
    #pragma unroll
    for (int i = 0; i < 4; ++i)
        #pragma unroll
        for (int j = 0; j < 4; ++j)
            #pragma unroll
            for (int q = 0; q < 4; ++q) acc[i][j][q] = 0.f;

    uint4 ra0 = *(const uint4*)(aSrc + 0);
    uint4 ra1 = *(const uint4*)(aSrc + 8);
    uint4 rb0 = *(const uint4*)(bSrc + 0);
    uint4 rb1 = *(const uint4*)(bSrc + 8);
    {
        uint4* dA = (uint4*)&sA[0][lhalf][lrow * STRB];
        dA[0] = ra0; dA[1] = ra1;
        uint4* dB = (uint4*)&sB[0][lhalf][lrow * STRB];
        dB[0] = rb0; dB[1] = rb1;
    }
    __syncthreads();

    for (int kt = 0; kt < 64; ++kt) {
        const int cur = kt & 1;
        if (kt < 63) {
            int k0 = (kt + 1) * 16;
            ra0 = *(const uint4*)(aSrc + k0);
            ra1 = *(const uint4*)(aSrc + k0 + 8);
            rb0 = *(const uint4*)(bSrc + k0);
            rb1 = *(const uint4*)(bSrc + k0 + 8);
        }

        const uint32_t aH = smA + (uint32_t)cur * 12288;
        const uint32_t aL = aH + 6144;
        const uint32_t bH = smB + (uint32_t)cur * 12288;
        const uint32_t bL = bH + 6144;

        uint32_t fbh[2][4], fbl[2][4];
        ldm_x4(fbh[0], bH + boff);
        ldm_x4(fbh[1], bH + boff + 16*STRB*2);
        ldm_x4(fbl[0], bL + boff);
        ldm_x4(fbl[1], bL + boff + 16*STRB*2);

        #pragma unroll
        for (int mi = 0; mi < 4; ++mi) {
            uint32_t fah[4], fal[4];
            ldm_x4(fah, aH + aoff + mi * 16*STRB*2);
            ldm_x4(fal, aL + aoff + mi * 16*STRB*2);
            #pragma unroll
            for (int nj = 0; nj < 4; ++nj) {
                int t = nj >> 1, s = nj & 1;
                float* c = acc[mi][nj];
                mma16816(c, fah, fbh[t][s], fbh[t][s+2]);
                mma16816(c, fah, fbl[t][s], fbl[t][s+2]);
                mma16816(c, fal, fbh[t][s], fbh[t][s+2]);
            }
        }

        if (kt < 63) {
            uint4* dA = (uint4*)&sA[cur ^ 1][lhalf][lrow * STRB];
            dA[0] = ra0; dA[1] = ra1;
            uint4* dB = (uint4*)&sB[cur ^ 1][lhalf][lrow * STRB];
            dB[0] = rb0; dB[1] = rb1;
            __syncthreads();
        }
    }

    // epilogue: bias + hi/lo split + scatter (Q scaled, V transposed)
    const int group = lane >> 2, tig = lane & 3;
    #pragma unroll
    for (int mi = 0; mi < 4; ++mi) {
        #pragma unroll
        for (int nj = 0; nj < 4; ++nj) {
            int nl = wn*32 + nj*8 + tig*2;
            int c  = n0 + nl;
            int g  = c >> 8, cc = c & 255;
            int hh = r + 4 * (cc >> 6), d = cc & 63;
            const float* barr = (g == 0) ? bq : (g == 1) ? bkv : bkv + 1024;
            float b0v = barr[hh*64 + d], b1v = barr[hh*64 + d + 1];
            #pragma unroll
            for (int half = 0; half < 2; ++half) {
                int jrow = m0 + wm*64 + mi*16 + group + half*8;
                int seg = jrow >> 9, p = jrow & 511;
                float vx = acc[mi][nj][half*2 + 0] + b0v;
                float vy = acc[mi][nj][half*2 + 1] + b1v;
                if (g == 0) { vx *= 0.125f; vy *= 0.125f; }
                __nv_bfloat16 hx = __float2bfloat16_rn(vx);
                __nv_bfloat16 hy = __float2bfloat16_rn(vy);
                __nv_bfloat16 lx = __float2bfloat16_rn(vx - __bfloat162float(hx));
                __nv_bfloat16 ly = __float2bfloat16_rn(vy - __bfloat162float(hy));
                long bsh = (long)((b*NSEG + seg)*NHEAD + hh);
                if (g < 2) {
                    long idx = (bsh*NPTS + p)*DHEAD + d;
                    __nv_bfloat16* H = (g == 0) ? g_Qh : g_Kh;
                    __nv_bfloat16* L = (g == 0) ? g_Ql : g_Kl;
                    __nv_bfloat162 hv; hv.x = hx; hv.y = hy;
                    __nv_bfloat162 lv; lv.x = lx; lv.y = ly;
                    *(__nv_bfloat162*)&H[idx] = hv;
                    *(__nv_bfloat162*)&L[idx] = lv;
                } else {
                    long idx = (bsh*DHEAD + d)*NPTS + p;
                    g_Vth[idx] = hx; g_Vth[idx + NPTS] = hy;
                    g_Vtl[idx] = lx; g_Vtl[idx + NPTS] = ly;
                }
            }
        }
    }
}

// ---------------------------------------------------------------------------
// Flash attention via bf16x3 mma. Block: (b,seg,h) x 128 q-rows; 8 warps,
// each warp 16 q-rows; 8 key-chunks of 64, online softmax, double-buffered.
// ---------------------------------------------------------------------------
#define BUFE (4*64*STR)

__global__ __launch_bounds__(256) void attn_mma(float* __restrict__ out)
{
    extern __shared__ __nv_bfloat16 sb[];
    const int tid = threadIdx.x;
    const int lane = tid & 31, warp = tid >> 5;
    const int qt = blockIdx.x, h = blockIdx.y, bs = blockIdx.z;
    const int b = bs >> 2, seg = bs & 3;
    const long base = (long)(bs*NHEAD + h) * (NPTS*DHEAD);

    const uint32_t sm0 = (uint32_t)__cvta_generic_to_shared(sb);

    // chunk loader: tid>>6 -> {Kh,Kl,Vh,Vl}, row tid&63, 128B per row
    const int lm = tid >> 6, lj = tid & 63;
    const __nv_bfloat16* csrc;
    if      (lm == 0) csrc = g_Kh  + base + lj*DHEAD;
    else if (lm == 1) csrc = g_Kl  + base + lj*DHEAD;
    else if (lm == 2) csrc = g_Vth + base + (long)lj*NPTS;
    else              csrc = g_Vtl + base + (long)lj*NPTS;
    const long cstep = (lm < 2) ? 64*DHEAD : 64;
    const uint32_t cdst = sm0 + (uint32_t)((lm*64 + lj)*STR)*2;

    // stage Q into buf1 + chunk0 into buf0
    {
        int qhf = tid >> 7, qrow = tid & 127;
        const __nv_bfloat16* qs = (qhf ? g_Ql : g_Qh) + base + (long)(qt*128 + qrow)*DHEAD;
        uint32_t qd = sm0 + (uint32_t)(BUFE + (qhf*128 + qrow)*STR)*2;
        #pragma unroll
        for (int i = 0; i < 8; ++i) cp16(qd + i*16, qs + i*8);
        #pragma unroll
        for (int i = 0; i < 8; ++i) cp16(cdst + i*16, csrc + i*8);
    }
    cp_commit();
    cp_waitall();
    __syncthreads();

    const int lrow16 = (lane & 7) + ((lane >> 3) & 1) * 8;
    const int kbyt   = (lane >> 4) * 16;

    uint32_t qh[4][4], ql[4][4];
    {
        uint32_t qa = sm0 + (uint32_t)(BUFE + (warp*16 + lrow16)*STR)*2 + kbyt;
        #pragma unroll
        for (int kk = 0; kk < 4; ++kk) {
            ldm_x4(qh[kk], qa + kk*32);
            ldm_x4(ql[kk], qa + 128*STR*2 + kk*32);
        }
    }
    __syncthreads();
    // chunk1 -> buf1
    {
        const __nv_bfloat16* s = csrc + cstep;
        uint32_t d = cdst + (uint32_t)BUFE*2;
        #pragma unroll
        for (int i = 0; i < 8; ++i) cp16(d + i*16, s + i*8);
    }
    cp_commit();

    float m0 = -1e30f, m1 = -1e30f, l0 = 0.f, l1 = 0.f;
    float o[8][4];
    #pragma unroll
    for (int j = 0; j < 8; ++j)
        #pragma unroll
        for (int q = 0; q < 4; ++q) o[j][q] = 0.f;

    for (int ck = 0; ck < 8; ++ck) {
        const uint32_t sK  = sm0 + (uint32_t)(ck & 1)*BUFE*2;
        const uint32_t sKl = sK + 64*STR*2;
        const uint32_t sV  = sK + 2*64*STR*2;
        const uint32_t sVl = sK + 3*64*STR*2;

        float sc[8][4];
        #pragma unroll
        for (int j = 0; j < 8; ++j)
            #pragma unroll
            for (int q = 0; q < 4; ++q) sc[j][q] = 0.f;

        #pragma unroll
        for (int kk = 0; kk < 4; ++kk) {
            uint32_t kbh[4][4], kbl[4][4];
            #pragma unroll
            for (int kg = 0; kg < 4; ++kg) {
                uint32_t a = (uint32_t)((kg*16 + lrow16)*STR*2 + kk*32 + kbyt);
                ldm_x4(kbh[kg], sK + a);
                ldm_x4(kbl[kg], sKl + a);
            }
            #pragma unroll
            for (int kg = 0; kg < 4; ++kg)
                #pragma unroll
                for (int s = 0; s < 2; ++s) {
                    float* c = sc[kg*2 + s];
                    mma16816(c, qh[kk], kbh[kg][s], kbh[kg][s+2]);
                    mma16816(c, ql[kk], kbh[kg][s], kbh[kg][s+2]);
                    mma16816(c, qh[kk], kbl[kg][s], kbl[kg][s+2]);
                }
        }

        // online softmax (scale pre-folded into Q)
        float mc0 = -1e30f, mc1 = -1e30f;
        #pragma unroll
        for (int j = 0; j < 8; ++j) {
            mc0 = fmaxf(mc0, fmaxf(sc[j][0], sc[j][1]));
            mc1 = fmaxf(mc1, fmaxf(sc[j][2], sc[j][3]));
        }
        mc0 = fmaxf(mc0, __shfl_xor_sync(0xffffffffu, mc0, 1));
        mc0 = fmaxf(mc0, __shfl_xor_sync(0xffffffffu, mc0, 2));
        mc1 = fmaxf(mc1, __shfl_xor_sync(0xffffffffu, mc1, 1));
        mc1 = fmaxf(mc1, __shfl_xor_sync(0xffffffffu, mc1, 2));
        float mn0 = fmaxf(m0, mc0), mn1 = fmaxf(m1, mc1);
        float a0 = __expf(m0 - mn0), a1 = __expf(m1 - mn1);
        float s0 = 0.f, s1 = 0.f;
        #pragma unroll
        for (int j = 0; j < 8; ++j) {
            sc[j][0] = __expf(sc[j][0] - mn0);
            sc[j][1] = __expf(sc[j][1] - mn0);
            sc[j][2] = __expf(sc[j][2] - mn1);
            sc[j][3] = __expf(sc[j][3] - mn1);
            s0 += sc[j][0] + sc[j][1];
            s1 += sc[j][2] + sc[j][3];
        }
        s0 += __shfl_xor_sync(0xffffffffu, s0, 1);
        s0 += __shfl_xor_sync(0xffffffffu, s0, 2);
        s1 += __shfl_xor_sync(0xffffffffu, s1, 1);
        s1 += __shfl_xor_sync(0xffffffffu, s1, 2);
        l0 = l0*a0 + s0; l1 = l1*a1 + s1;
        m0 = mn0; m1 = mn1;
        #pragma unroll
        for (int j = 0; j < 8; ++j) {
            o[j][0] *= a0; o[j][1] *= a0;
            o[j][2] *= a1; o[j][3] *= a1;
        }

        // P -> A-fragments (hi/lo)
        uint32_t ph[4][4], pl[4][4];
        #pragma unroll
        for (int t = 0; t < 4; ++t) {
            pack_hl(sc[2*t  ][0], sc[2*t  ][1], ph[t][0], pl[t][0]);
            pack_hl(sc[2*t  ][2], sc[2*t  ][3], ph[t][1], pl[t][1]);
            pack_hl(sc[2*t+1][0], sc[2*t+1][1], ph[t][2], pl[t][2]);
            pack_hl(sc[2*t+1][2], sc[2*t+1][3], ph[t][3], pl[t][3]);
        }

        // O += P V
        #pragma unroll
        for (int t = 0; t < 4; ++t) {
            uint32_t vbh[4][4], vbl[4][4];
            #pragma unroll
            for (int nt = 0; nt < 4; ++nt) {
                uint32_t a = (uint32_t)((nt*16 + lrow16)*STR*2 + t*32 + kbyt);
                ldm_x4(vbh[nt], sV + a);
                ldm_x4(vbl[nt], sVl + a);
            }
            #pragma unroll
            for (int nt = 0; nt < 4; ++nt)
                #pragma unroll
                for (int s = 0; s < 2; ++s) {
                    float* c = o[nt*2 + s];
                    mma16816(c, ph[t], vbh[nt][s], vbh[nt][s+2]);
                    mma16816(c, pl[t], vbh[nt][s], vbh[nt][s+2]);
                    mma16816(c, ph[t], vbl[nt][s], vbl[nt][s+2]);
                }
        }

        cp_waitall();
        __syncthreads();
        if (ck + 2 < 8) {
            const __nv_bfloat16* s = csrc + (long)(ck + 2)*cstep;
            uint32_t d = cdst + (uint32_t)(ck & 1)*BUFE*2;
            #pragma unroll
            for (int i = 0; i < 8; ++i) cp16(d + i*16, s + i*8);
            cp_commit();
        }
    }

    // epilogue: normalize + scattered fp32 write
    float inv0 = 1.f / l0, inv1 = 1.f / l1;
    int r0 = lane >> 2, dc = (lane & 3) * 2;
    int p0 = qt*128 + warp*16 + r0;
    int s0p = seg*WSEG + 4*p0 + (h & 3);
    int s1p = s0p + 32;    // p+8 -> +32 positions
    float* ob0 = out + ((long)b*SLEN + s0p)*HID + h*DHEAD + dc;
    float* ob1 = out + ((long)b*SLEN + s1p)*HID + h*DHEAD + dc;
    #pragma unroll
    for (int j = 0; j < 8; ++j) {
        float2 v0 = make_float2(o[j][0]*inv0, o[j][1]*inv0);
        float2 v1 = make_float2(o[j][2]*inv1, o[j][3]*inv1);
        *(float2*)(ob0 + j*8) = v0;
        *(float2*)(ob1 + j*8) = v1;
    }
}

// ---------------------------------------------------------------------------
extern "C" void kernel_launch(void* const* d_in, const int* in_sizes, int n_in,
                              void* d_out, int out_size)
{
    const float* X   = (const float*)d_in[0];
    const float* Wq  = (const float*)d_in[1];
    const float* bq  = (const float*)d_in[2];
    const float* Wkv = (const float*)d_in[3];
    const float* bkv = (const float*)d_in[4];
    float* out = (float*)d_out;

    cudaMemsetAsync(out, 0, (size_t)out_size * sizeof(float), 0);

    splitx<<<BATCH*SLEN*HID/4/256, 256>>>((const float4*)X);

    dim3 gw(HID/32, NCOL/32, 4);
    wpack<<<gw, 256>>>(Wq, Wkv);

    dim3 g1(NCOL/128, 16, BATCH * 4);
    proj_mma<<<g1, 256>>>(bq, bkv);

    const int smem = 2 * BUFE * (int)sizeof(__nv_bfloat16);   // 73728 B
    cudaFuncSetAttribute(attn_mma, cudaFuncAttributeMaxDynamicSharedMemorySize, smem);
    dim3 g2(4, NHEAD, BATCH * NSEG);
    attn_mma<<<g2, 256, smem>>>(out);
}

// round 6
// speedup vs baseline: 3.1635x; 1.4637x over previous
#include <cuda_runtime.h>
#include <cuda_fp16.h>
#include <cstdint>

#define BATCH 2
#define SLEN  8192
#define HID   1024
#define NSEG  4
#define NPTS  512
#define NHEAD 16
#define DHEAD 64
#define WSEG  2048
#define NCOL  768
#define STRB  24   // proj smem stride (fp16)
#define STR   72   // attn smem stride (fp16)

#define GSIZE (BATCH*NSEG*NHEAD*NPTS*DHEAD)
__device__ __align__(16) __half g_Xh[BATCH*SLEN*HID];
__device__ __align__(16) __half g_Xl[BATCH*SLEN*HID];
__device__ __align__(16) __half g_Wp[4*NCOL*HID];             // [r][n][k] hi only
__device__ __align__(16) __half g_Qh[GSIZE], g_Ql[GSIZE];     // [b][seg][h][p][d], pre-scaled
__device__ __align__(16) __half g_Kh[GSIZE];                  // [b][seg][h][p][d]
__device__ __align__(16) __half g_Vth[GSIZE], g_Vtl[GSIZE];   // [b][seg][h][d][p]

// ---------------------------------------------------------------------------
__device__ __forceinline__ void ldm_x4(uint32_t* r, uint32_t addr) {
    asm volatile("ldmatrix.sync.aligned.m8n8.x4.shared.b16 {%0,%1,%2,%3}, [%4];\n"
                 : "=r"(r[0]), "=r"(r[1]), "=r"(r[2]), "=r"(r[3]) : "r"(addr));
}
__device__ __forceinline__ void mma16816(float* c, const uint32_t* a,
                                         uint32_t b0, uint32_t b1) {
    asm volatile("mma.sync.aligned.m16n8k16.row.col.f32.f16.f16.f32 "
                 "{%0,%1,%2,%3}, {%4,%5,%6,%7}, {%8,%9}, {%0,%1,%2,%3};\n"
                 : "+f"(c[0]), "+f"(c[1]), "+f"(c[2]), "+f"(c[3])
                 : "r"(a[0]), "r"(a[1]), "r"(a[2]), "r"(a[3]), "r"(b0), "r"(b1));
}
__device__ __forceinline__ void cp16(uint32_t dst, const void* src) {
    asm volatile("cp.async.cg.shared.global [%0], [%1], 16;\n" :: "r"(dst), "l"(src));
}
__device__ __forceinline__ void cp_commit() { asm volatile("cp.async.commit_group;\n"); }
__device__ __forceinline__ void cp_waitall() { asm volatile("cp.async.wait_group 0;\n"); }

__device__ __forceinline__ void pack_hl(float x, float y, uint32_t& hi, uint32_t& lo) {
    __half hx = __float2half_rn(x), hy = __float2half_rn(y);
    __half lx = __float2half_rn(x - __half2float(hx));
    __half ly = __float2half_rn(y - __half2float(hy));
    __half2 h2; h2.x = hx; h2.y = hy;
    __half2 l2; l2.x = lx; l2.y = ly;
    hi = *(uint32_t*)&h2; lo = *(uint32_t*)&l2;
}

// ---------------------------------------------------------------------------
__global__ __launch_bounds__(256) void splitx(const float4* __restrict__ X4)
{
    long i = (long)blockIdx.x * 256 + threadIdx.x;
    float4 v = X4[i];
    __half2 h01, h23, l01, l23;
    h01.x = __float2half_rn(v.x); h01.y = __float2half_rn(v.y);
    h23.x = __float2half_rn(v.z); h23.y = __float2half_rn(v.w);
    l01.x = __float2half_rn(v.x - __half2float(h01.x));
    l01.y = __float2half_rn(v.y - __half2float(h01.y));
    l23.x = __float2half_rn(v.z - __half2float(h23.x));
    l23.y = __float2half_rn(v.w - __half2float(h23.y));
    __half2* H2 = (__half2*)g_Xh;
    __half2* L2 = (__half2*)g_Xl;
    H2[2*i] = h01; H2[2*i+1] = h23;
    L2[2*i] = l01; L2[2*i+1] = l23;
}

// ---------------------------------------------------------------------------
__global__ __launch_bounds__(256) void wpack(const float* __restrict__ Wq,
                                             const float* __restrict__ Wkv)
{
    __shared__ float s[32][33];
    int tx = threadIdx.x & 31, ty = threadIdx.x >> 5;
    int r = blockIdx.z;
    int n = blockIdx.y * 32 + tx;
    int g = n >> 8, cc = n & 255;
    int h = r + 4 * (cc >> 6), d = cc & 63;
    const float* src; long stride;
    if (g == 0)      { src = Wq  + h*64 + d;        stride = 1024; }
    else if (g == 1) { src = Wkv + h*64 + d;        stride = 2048; }
    else             { src = Wkv + 1024 + h*64 + d; stride = 2048; }
    #pragma unroll
    for (int i = 0; i < 4; ++i) {
        int k = blockIdx.x * 32 + ty + i * 8;
        s[ty + i*8][tx] = src[(long)k * stride];
    }
    __syncthreads();
    long rbase = (long)r * NCOL * HID;
    #pragma unroll
    for (int i = 0; i < 4; ++i) {
        int nl = ty + i * 8;
        float v = s[tx][nl];
        long idx = (long)(blockIdx.y * 32 + nl) * HID + blockIdx.x * 32 + tx;
        g_Wp[rbase + idx] = __float2half_rn(v);
    }
}

// ---------------------------------------------------------------------------
// proj via fp16x2 mma: C = (Xh + Xl) @ Wh.  128x128 tile, k16 double-buffered.
// Epilogue: +bias; Q scaled 1/8, hi/lo; K single; V hi/lo transposed.
// ---------------------------------------------------------------------------
__global__ __launch_bounds__(256) void proj_mma(const float* __restrict__ bq,
                                                const float* __restrict__ bkv)
{
    __shared__ __half sA[2][2][128*STRB];
    __shared__ __half sB[2][128*STRB];

    const int tid  = threadIdx.x;
    const int lane = tid & 31, warp = tid >> 5;
    const int wm = warp >> 2, wn = warp & 3;
    const int b  = blockIdx.z >> 2;
    const int r  = blockIdx.z & 3;
    const int m0 = blockIdx.y * 128;
    const int n0 = blockIdx.x * 128;

    const int lrow = tid & 127, lhalf = tid >> 7;
    const __half* aSrc =
        (lhalf ? g_Xl : g_Xh) + ((long)b * SLEN + (4*(m0 + lrow) + r)) * HID;
    const __half* bSrc = g_Wp + ((long)r * NCOL + n0 + lrow) * HID;

    const int lrow16 = (lane & 7) + ((lane >> 3) & 1) * 8;
    const int kbyt   = (lane >> 4) * 16;
    const uint32_t smA = (uint32_t)__cvta_generic_to_shared(&sA[0][0][0]);
    const uint32_t smB = (uint32_t)__cvta_generic_to_shared(&sB[0][0]);
    const uint32_t aoff = (uint32_t)((wm*64 + lrow16) * STRB * 2 + kbyt);
    const uint32_t boff = (uint32_t)((wn*32 + lrow16) * STRB * 2 + kbyt);

    float acc[4][4][4];
    #pragma unroll
    for (int i = 0; i < 4; ++i)
        #pragma unroll
        for (int j = 0; j < 4; ++j)
            #pragma unroll
            for (int q = 0; q < 4; ++q) acc[i][j][q] = 0.f;

    uint4 ra0 = *(const uint4*)(aSrc + 0);
    uint4 ra1 = *(const uint4*)(aSrc + 8);
    uint4 rb0, rb1;
    if (lhalf == 0) { rb0 = *(const uint4*)(bSrc + 0); rb1 = *(const uint4*)(bSrc + 8); }
    {
        uint4* dA = (uint4*)&sA[0][lhalf][lrow * STRB];
        dA[0] = ra0; dA[1] = ra1;
        if (lhalf == 0) {
            uint4* dB = (uint4*)&sB[0][lrow * STRB];
            dB[0] = rb0; dB[1] = rb1;
        }
    }
    __syncthreads();

    for (int kt = 0; kt < 64; ++kt) {
        const int cur = kt & 1;
        if (kt < 63) {
            int k0 = (kt + 1) * 16;
            ra0 = *(const uint4*)(aSrc + k0);
            ra1 = *(const uint4*)(aSrc + k0 + 8);
            if (lhalf == 0) {
                rb0 = *(const uint4*)(bSrc + k0);
                rb1 = *(const uint4*)(bSrc + k0 + 8);
            }
        }

        const uint32_t aH = smA + (uint32_t)cur * 12288;
        const uint32_t aL = aH + 6144;
        const uint32_t bH = smB + (uint32_t)cur * 6144;

        uint32_t fbh[2][4];
        ldm_x4(fbh[0], bH + boff);
        ldm_x4(fbh[1], bH + boff + 16*STRB*2);

        #pragma unroll
        for (int mi = 0; mi < 4; ++mi) {
            uint32_t fah[4], fal[4];
            ldm_x4(fah, aH + aoff + mi * 16*STRB*2);
            ldm_x4(fal, aL + aoff + mi * 16*STRB*2);
            #pragma unroll
            for (int nj = 0; nj < 4; ++nj) {
                int t = nj >> 1, s = nj & 1;
                float* c = acc[mi][nj];
                mma16816(c, fah, fbh[t][s], fbh[t][s+2]);
                mma16816(c, fal, fbh[t][s], fbh[t][s+2]);
            }
        }

        if (kt < 63) {
            uint4* dA = (uint4*)&sA[cur ^ 1][lhalf][lrow * STRB];
            dA[0] = ra0; dA[1] = ra1;
            if (lhalf == 0) {
                uint4* dB = (uint4*)&sB[cur ^ 1][lrow * STRB];
                dB[0] = rb0; dB[1] = rb1;
            }
            __syncthreads();
        }
    }

    // epilogue
    const int group = lane >> 2, tig = lane & 3;
    #pragma unroll
    for (int mi = 0; mi < 4; ++mi) {
        #pragma unroll
        for (int nj = 0; nj < 4; ++nj) {
            int nl = wn*32 + nj*8 + tig*2;
            int c  = n0 + nl;
            int g  = c >> 8, cc = c & 255;
            int hh = r + 4 * (cc >> 6), d = cc & 63;
            const float* barr = (g == 0) ? bq : (g == 1) ? bkv : bkv + 1024;
            float b0v = barr[hh*64 + d], b1v = barr[hh*64 + d + 1];
            #pragma unroll
            for (int half = 0; half < 2; ++half) {
                int jrow = m0 + wm*64 + mi*16 + group + half*8;
                int seg = jrow >> 9, p = jrow & 511;
                float vx = acc[mi][nj][half*2 + 0] + b0v;
                float vy = acc[mi][nj][half*2 + 1] + b1v;
                long bsh = (long)((b*NSEG + seg)*NHEAD + hh);
                if (g == 0) {
                    vx *= 0.125f; vy *= 0.125f;
                    uint32_t hi, lo;
                    pack_hl(vx, vy, hi, lo);
                    long idx = (bsh*NPTS + p)*DHEAD + d;
                    *(uint32_t*)&g_Qh[idx] = hi;
                    *(uint32_t*)&g_Ql[idx] = lo;
                } else if (g == 1) {
                    __half2 hv; hv.x = __float2half_rn(vx); hv.y = __float2half_rn(vy);
                    long idx = (bsh*NPTS + p)*DHEAD + d;
                    *(__half2*)&g_Kh[idx] = hv;
                } else {
                    __half hx = __float2half_rn(vx), hy = __float2half_rn(vy);
                    __half lx = __float2half_rn(vx - __half2float(hx));
                    __half ly = __float2half_rn(vy - __half2float(hy));
                    long idx = (bsh*DHEAD + d)*NPTS + p;
                    g_Vth[idx] = hx; g_Vth[idx + NPTS] = hy;
                    g_Vtl[idx] = lx; g_Vtl[idx + NPTS] = ly;
                }
            }
        }
    }
}

// ---------------------------------------------------------------------------
// Flash attention, fp16: S = (Qh+Ql)Kh (2-term); O = (Ph+Pl)Vh + Ph Vl (3-term).
// Chunk buffers: K(64) + Vh(64) + Vl(64) rows; Q zone 256 rows separate.
// ---------------------------------------------------------------------------
#define BUFE (192*STR)
#define QOFF (2*BUFE)

__global__ __launch_bounds__(256) void attn_mma(float* __restrict__ out)
{
    extern __shared__ __half sbm[];
    const int tid = threadIdx.x;
    const int lane = tid & 31, warp = tid >> 5;
    const int qt = blockIdx.x, h = blockIdx.y, bs = blockIdx.z;
    const int b = bs >> 2, seg = bs & 3;
    const long base = (long)(bs*NHEAD + h) * (NPTS*DHEAD);

    const uint32_t sm0 = (uint32_t)__cvta_generic_to_shared(sbm);

    // chunk loader: threads 0-191, one full 128B row each
    const int lm = tid / 64, lj = tid & 63;
    const bool ldr = tid < 192;
    const __half* csrc = nullptr;
    long cstep = 0;
    uint32_t cdst = 0;
    if (ldr) {
        if      (lm == 0) { csrc = g_Kh  + base + lj*DHEAD;      cstep = 64*DHEAD; }
        else if (lm == 1) { csrc = g_Vth + base + (long)lj*NPTS; cstep = 64; }
        else              { csrc = g_Vtl + base + (long)lj*NPTS; cstep = 64; }
        cdst = sm0 + (uint32_t)((lm*64 + lj)*STR)*2;
    }

    // stage Q (zone) + chunk0 (buf0)
    {
        int qhf = tid >> 7, qrow = tid & 127;
        const __half* qs = (qhf ? g_Ql : g_Qh) + base + (long)(qt*128 + qrow)*DHEAD;
        uint32_t qd = sm0 + (uint32_t)(QOFF + (qhf*128 + qrow)*STR)*2;
        #pragma unroll
        for (int i = 0; i < 8; ++i) cp16(qd + i*16, qs + i*8);
        if (ldr) {
            #pragma unroll
            for (int i = 0; i < 8; ++i) cp16(cdst + i*16, csrc + i*8);
        }
    }
    cp_commit();
    cp_waitall();
    __syncthreads();

    const int lrow16 = (lane & 7) + ((lane >> 3) & 1) * 8;
    const int kbyt   = (lane >> 4) * 16;

    uint32_t qh[4][4], ql[4][4];
    {
        uint32_t qa = sm0 + (uint32_t)(QOFF + (warp*16 + lrow16)*STR)*2 + kbyt;
        #pragma unroll
        for (int kk = 0; kk < 4; ++kk) {
            ldm_x4(qh[kk], qa + kk*32);
            ldm_x4(ql[kk], qa + 128*STR*2 + kk*32);
        }
    }
    // chunk1 -> buf1 (Q zone untouched)
    if (ldr) {
        const __half* s = csrc + cstep;
        uint32_t d = cdst + (uint32_t)BUFE*2;
        #pragma unroll
        for (int i = 0; i < 8; ++i) cp16(d + i*16, s + i*8);
    }
    cp_commit();

    float m0 = -1e30f, m1 = -1e30f, l0 = 0.f, l1 = 0.f;
    float o[8][4];
    #pragma unroll
    for (int j = 0; j < 8; ++j)
        #pragma unroll
        for (int q = 0; q < 4; ++q) o[j][q] = 0.f;

    for (int ck = 0; ck < 8; ++ck) {
        const uint32_t sK  = sm0 + (uint32_t)(ck & 1)*BUFE*2;
        const uint32_t sV  = sK + 64*STR*2;
        const uint32_t sVl = sK + 128*STR*2;

        float sc[8][4];
        #pragma unroll
        for (int j = 0; j < 8; ++j)
            #pragma unroll
            for (int q = 0; q < 4; ++q) sc[j][q] = 0.f;

        #pragma unroll
        for (int kk = 0; kk < 4; ++kk) {
            uint32_t kbh[4][4];
            #pragma unroll
            for (int kg = 0; kg < 4; ++kg) {
                uint32_t a = (uint32_t)((kg*16 + lrow16)*STR*2 + kk*32 + kbyt);
                ldm_x4(kbh[kg], sK + a);
            }
            #pragma unroll
            for (int kg = 0; kg < 4; ++kg)
                #pragma unroll
                for (int s = 0; s < 2; ++s) {
                    float* c = sc[kg*2 + s];
                    mma16816(c, qh[kk], kbh[kg][s], kbh[kg][s+2]);
                    mma16816(c, ql[kk], kbh[kg][s], kbh[kg][s+2]);
                }
        }

        // online softmax
        float mc0 = -1e30f, mc1 = -1e30f;
        #pragma unroll
        for (int j = 0; j < 8; ++j) {
            mc0 = fmaxf(mc0, fmaxf(sc[j][0], sc[j][1]));
            mc1 = fmaxf(mc1, fmaxf(sc[j][2], sc[j][3]));
        }
        mc0 = fmaxf(mc0, __shfl_xor_sync(0xffffffffu, mc0, 1));
        mc0 = fmaxf(mc0, __shfl_xor_sync(0xffffffffu, mc0, 2));
        mc1 = fmaxf(mc1, __shfl_xor_sync(0xffffffffu, mc1, 1));
        mc1 = fmaxf(mc1, __shfl_xor_sync(0xffffffffu, mc1, 2));
        float mn0 = fmaxf(m0, mc0), mn1 = fmaxf(m1, mc1);
        float a0 = __expf(m0 - mn0), a1 = __expf(m1 - mn1);
        float s0 = 0.f, s1 = 0.f;
        #pragma unroll
        for (int j = 0; j < 8; ++j) {
            sc[j][0] = __expf(sc[j][0] - mn0);
            sc[j][1] = __expf(sc[j][1] - mn0);
            sc[j][2] = __expf(sc[j][2] - mn1);
            sc[j][3] = __expf(sc[j][3] - mn1);
            s0 += sc[j][0] + sc[j][1];
            s1 += sc[j][2] + sc[j][3];
        }
        s0 += __shfl_xor_sync(0xffffffffu, s0, 1);
        s0 += __shfl_xor_sync(0xffffffffu, s0, 2);
        s1 += __shfl_xor_sync(0xffffffffu, s1, 1);
        s1 += __shfl_xor_sync(0xffffffffu, s1, 2);
        l0 = l0*a0 + s0; l1 = l1*a1 + s1;
        m0 = mn0; m1 = mn1;
        #pragma unroll
        for (int j = 0; j < 8; ++j) {
            o[j][0] *= a0; o[j][1] *= a0;
            o[j][2] *= a1; o[j][3] *= a1;
        }

        // P -> A-frags (hi/lo)
        uint32_t ph[4][4], pl[4][4];
        #pragma unroll
        for (int t = 0; t < 4; ++t) {
            pack_hl(sc[2*t  ][0], sc[2*t  ][1], ph[t][0], pl[t][0]);
            pack_hl(sc[2*t  ][2], sc[2*t  ][3], ph[t][1], pl[t][1]);
            pack_hl(sc[2*t+1][0], sc[2*t+1][1], ph[t][2], pl[t][2]);
            pack_hl(sc[2*t+1][2], sc[2*t+1][3], ph[t][3], pl[t][3]);
        }

        // O += (Ph+Pl) Vh + Ph Vl
        #pragma unroll
        for (int t = 0; t < 4; ++t) {
            uint32_t vbh[4][4], vbl[4][4];
            #pragma unroll
            for (int nt = 0; nt < 4; ++nt) {
                uint32_t a = (uint32_t)((nt*16 + lrow16)*STR*2 + t*32 + kbyt);
                ldm_x4(vbh[nt], sV + a);
                ldm_x4(vbl[nt], sVl + a);
            }
            #pragma unroll
            for (int nt = 0; nt < 4; ++nt)
                #pragma unroll
                for (int s = 0; s < 2; ++s) {
                    float* c = o[nt*2 + s];
                    mma16816(c, ph[t], vbh[nt][s], vbh[nt][s+2]);
                    mma16816(c, pl[t], vbh[nt][s], vbh[nt][s+2]);
                    mma16816(c, ph[t], vbl[nt][s], vbl[nt][s+2]);
                }
        }

        cp_waitall();
        __syncthreads();
        if (ck + 2 < 8 && ldr) {
            const __half* s = csrc + (long)(ck + 2)*cstep;
            uint32_t d = cdst + (uint32_t)(ck & 1)*BUFE*2;
            #pragma unroll
            for (int i = 0; i < 8; ++i) cp16(d + i*16, s + i*8);
        }
        if (ck + 2 < 8) cp_commit();
    }

    // epilogue
    float inv0 = 1.f / l0, inv1 = 1.f / l1;
    int r0 = lane >> 2, dc = (lane & 3) * 2;
    int p0 = qt*128 + warp*16 + r0;
    int s0p = seg*WSEG + 4*p0 + (h & 3);
    int s1p = s0p + 32;
    float* ob0 = out + ((long)b*SLEN + s0p)*HID + h*DHEAD + dc;
    float* ob1 = out + ((long)b*SLEN + s1p)*HID + h*DHEAD + dc;
    #pragma unroll
    for (int j = 0; j < 8; ++j) {
        float2 v0 = make_float2(o[j][0]*inv0, o[j][1]*inv0);
        float2 v1 = make_float2(o[j][2]*inv1, o[j][3]*inv1);
        *(float2*)(ob0 + j*8) = v0;
        *(float2*)(ob1 + j*8) = v1;
    }
}

// ---------------------------------------------------------------------------
extern "C" void kernel_launch(void* const* d_in, const int* in_sizes, int n_in,
                              void* d_out, int out_size)
{
    const float* X   = (const float*)d_in[0];
    const float* Wq  = (const float*)d_in[1];
    const float* bq  = (const float*)d_in[2];
    const float* Wkv = (const float*)d_in[3];
    const float* bkv = (const float*)d_in[4];
    float* out = (float*)d_out;

    cudaMemsetAsync(out, 0, (size_t)out_size * sizeof(float), 0);

    splitx<<<BATCH*SLEN*HID/4/256, 256>>>((const float4*)X);

    dim3 gw(HID/32, NCOL/32, 4);
    wpack<<<gw, 256>>>(Wq, Wkv);

    dim3 g1(NCOL/128, 16, BATCH * 4);
    proj_mma<<<g1, 256>>>(bq, bkv);

    const int smem = (2*BUFE + 256*STR) * (int)sizeof(__half);   // 92160 B
    cudaFuncSetAttribute(attn_mma, cudaFuncAttributeMaxDynamicSharedMemorySize, smem);
    dim3 g2(4, NHEAD, BATCH * NSEG);
    attn_mma<<<g2, 256, smem>>>(out);
}